// round 14
// baseline (speedup 1.0000x reference)
#include <cuda_runtime.h>
#include <math.h>
#include <stdint.h>

#define B_    32
#define C_    256
#define HWP   256
#define NROWS 8192
#define NBUF  100000
#define DD    266
#define TOPK_ 32
#define EPS_  1e-5f
#define CAP_  8192

__device__ __align__(16) float g_out1[B_*C_*HWP];
__device__ __align__(16) float g_wt[9*256*256];
__device__ __align__(16) float g_wt2[9*256*256];
__device__ float g_t[NROWS*C_];
__device__ float g_q[NROWS*64];
__device__ float g_e0[B_*256];
__device__ float g_scores[B_*NBUF];
__device__ int   g_idx[B_*TOPK_];
__device__ float g_k[B_*TOPK_*64];
__device__ float g_v[B_*TOPK_*64];
__device__ float g_o[NROWS*64];
__device__ float g_lnf[NROWS*C_];
__device__ __align__(16) unsigned g_hist[32*65536];
__device__ unsigned g_thresh[32];
__device__ float g_cv[32*CAP_];
__device__ int   g_ci[32*CAP_];
__device__ int   g_cc[32];

__device__ __forceinline__ float wsum(float v){
    v += __shfl_xor_sync(0xffffffffu, v, 16);
    v += __shfl_xor_sync(0xffffffffu, v, 8);
    v += __shfl_xor_sync(0xffffffffu, v, 4);
    v += __shfl_xor_sync(0xffffffffu, v, 2);
    v += __shfl_xor_sync(0xffffffffu, v, 1);
    return v;
}
__device__ __forceinline__ float gelu_exact(float v){
    return 0.5f * v * (1.0f + erff(v * 0.7071067811865476f));
}
__device__ __forceinline__ float to_tf32(float x){
    uint32_t u;
    asm("cvt.rna.tf32.f32 %0, %1;" : "=r"(u) : "f"(x));
    return __uint_as_float(u);
}
__device__ __forceinline__ void mma8(float* c, const uint32_t* a, uint32_t b0, uint32_t b1){
    asm volatile("mma.sync.aligned.m16n8k8.row.col.f32.tf32.tf32.f32 "
        "{%0,%1,%2,%3},{%4,%5,%6,%7},{%8,%9},{%0,%1,%2,%3};"
        : "+f"(c[0]),"+f"(c[1]),"+f"(c[2]),"+f"(c[3])
        : "r"(a[0]),"r"(a[1]),"r"(a[2]),"r"(a[3]),"r"(b0),"r"(b1));
}
__device__ __forceinline__ unsigned fkey(float f){
    unsigned u = __float_as_uint(f);
    return (u & 0x80000000u) ? ~u : (u | 0x80000000u);
}
__device__ __forceinline__ void cp4(uint32_t s, const void* g){
    asm volatile("cp.async.ca.shared.global [%0], [%1], 4;" :: "r"(s), "l"(g));
}
__device__ __forceinline__ void cp8(uint32_t s, const void* g){
    asm volatile("cp.async.ca.shared.global [%0], [%1], 8;" :: "r"(s), "l"(g));
}
#define CP_COMMIT() asm volatile("cp.async.commit_group;")
template<int N>
__device__ __forceinline__ void cp_wait(){
    asm volatile("cp.async.wait_group %0;" :: "n"(N));
}

// ============ coalesced weight transpose + hist/cc zero ============
__global__ __launch_bounds__(256)
void wtrans2_kernel(const float* __restrict__ wa, const float* __restrict__ wb){
    __shared__ float tile[32][73];
    int bid = blockIdx.x;
    int which = bid >> 8;
    int t2 = bid & 255;
    int cob = t2 >> 5;
    int cib = t2 & 31;
    const float* w = which ? wb : wa;
    float* dst = which ? g_wt2 : g_wt;
    int tid = threadIdx.x;
    for (unsigned i = bid*256u + tid; i < 32u*65536u; i += 512u*256u) g_hist[i] = 0u;
    if (bid == 0 && tid < 32) g_cc[tid] = 0;
    for (int i = tid; i < 2304; i += 256){
        int co = i / 72, e = i % 72;
        tile[co][e] = to_tf32(w[(long)(cob*32+co)*2304 + cib*72 + e]);
    }
    __syncthreads();
    for (int i = tid; i < 2304; i += 256){
        int p = i >> 5, co = i & 31;
        int ci_l = p / 9, tap = p % 9;
        dst[((long)tap*256 + cib*8 + ci_l)*256 + cob*32 + co] = tile[co][ci_l*9+tap];
    }
}

// ============ conv v4: 256 blocks (co quarters), 256 thr, 2 blocks/SM ============
#define AS_BUF (9*8*72)      // 5184
#define XS_BUF (8*328)       // 2624
template<int WHICH>
__global__ __launch_bounds__(256,2)
void conv_mma_kernel(const float* __restrict__ x,
                     const float* __restrict__ bg, const float* __restrict__ bb){
    extern __shared__ float sm[];
    float* As = sm;                  // 2 * 5184
    float* Xs = sm + 2*AS_BUF;       // 2 * 2624

    int tid  = threadIdx.x;
    int lane = tid & 31, wid = tid >> 5;     // 8 warps
    int gid  = lane >> 2, tig = lane & 3;
    int warp_m = wid & 1, warp_n = wid >> 1; // 2m x 4n

    int bi  = blockIdx.x >> 3;
    int co0 = ((blockIdx.x >> 1) & 3) << 6;  // co quarter (64)
    int n0  = (blockIdx.x & 1) << 7;         // pixel half (128)

    const float* xin = (WHICH == 1) ? x : (const float*)g_out1;
    const float* wptr = (WHICH == 1) ? g_wt : g_wt2;

    for (int i = tid; i < 2*XS_BUF; i += 256) Xs[i] = 0.0f;

    float acc[2][4][4];
    #pragma unroll
    for (int h2 = 0; h2 < 2; h2++)
      #pragma unroll
      for (int jn = 0; jn < 4; jn++)
        #pragma unroll
        for (int i = 0; i < 4; i++) acc[h2][jn][i] = 0.0f;

    int bp[4];
    #pragma unroll
    for (int jn = 0; jn < 4; jn++){
        int p = n0 + warp_n*32 + jn*8 + gid;
        bp[jn] = (p >> 4)*18 + (p & 15);
    }

    int a_row = tid >> 5;            // 0..7 ci
    int a_col = (tid & 31) << 1;     // 0..62 co pairs
    int xp    = tid;                 // 0..255 pixel
    int pr    = ((xp >> 4) + 1)*18 + (xp & 15) + 1;

    uint32_t as_b = (uint32_t)__cvta_generic_to_shared(As);
    uint32_t xs_b = (uint32_t)__cvta_generic_to_shared(Xs);

    auto stage = [&](int cg){
        int bf = cg & 1;
        int ci0 = cg << 3;
        uint32_t ad = as_b + (uint32_t)(bf*AS_BUF + a_row*72 + a_col)*4u;
        const float* ws = wptr + ((ci0 + a_row) << 8) + co0 + a_col;
        #pragma unroll
        for (int tap = 0; tap < 9; tap++)
            cp8(ad + (uint32_t)tap*576u*4u, ws + (tap << 16));
        const float* xb = xin + ((long)bi*256 + ci0)*256 + xp;
        uint32_t xd = xs_b + (uint32_t)(bf*XS_BUF + pr)*4u;
        #pragma unroll
        for (int cr = 0; cr < 8; cr++)
            cp4(xd + (uint32_t)cr*328u*4u, xb + cr*256);
    };

    __syncthreads();
    stage(0);
    CP_COMMIT();

    int mb = warp_m*32;
    for (int cg = 0; cg < 32; cg++){
        cp_wait<0>();
        __syncthreads();
        if (cg + 1 < 32){ stage(cg + 1); CP_COMMIT(); }
        int bf = cg & 1;
        const float* Xb = &Xs[bf*XS_BUF];
        #pragma unroll
        for (int tap = 0; tap < 9; tap++){
            int toff = (tap/3)*18 + (tap%3);
            const float* Ab = &As[bf*AS_BUF + tap*576];
            uint32_t a[2][4];
            #pragma unroll
            for (int h2 = 0; h2 < 2; h2++){
                int m0 = mb + h2*16;
                a[h2][0] = __float_as_uint(Ab[tig*72 + m0 + gid]);
                a[h2][1] = __float_as_uint(Ab[tig*72 + m0 + gid + 8]);
                a[h2][2] = __float_as_uint(Ab[(tig+4)*72 + m0 + gid]);
                a[h2][3] = __float_as_uint(Ab[(tig+4)*72 + m0 + gid + 8]);
            }
            #pragma unroll
            for (int jn = 0; jn < 4; jn++){
                uint32_t b0 = __float_as_uint(Xb[tig*328 + bp[jn] + toff]);
                uint32_t b1 = __float_as_uint(Xb[(tig+4)*328 + bp[jn] + toff]);
                mma8(acc[0][jn], a[0], b0, b1);
                mma8(acc[1][jn], a[1], b0, b1);
            }
        }
    }

    if (WHICH == 1){
        #pragma unroll
        for (int h2 = 0; h2 < 2; h2++){
            int co = co0 + mb + h2*16 + gid;
            float g0 = bg[co],   b0v = bb[co];
            float g1 = bg[co+8], b1v = bb[co+8];
            float* o0 = g_out1 + ((long)bi*256 + co)*256;
            float* o1 = g_out1 + ((long)bi*256 + co + 8)*256;
            #pragma unroll
            for (int jn = 0; jn < 4; jn++){
                int col = n0 + warp_n*32 + jn*8 + tig*2;
                *(float2*)(o0 + col) = make_float2(
                    fmaxf(acc[h2][jn][0]*g0 + b0v, 0.f),
                    fmaxf(acc[h2][jn][1]*g0 + b0v, 0.f));
                *(float2*)(o1 + col) = make_float2(
                    fmaxf(acc[h2][jn][2]*g1 + b1v, 0.f),
                    fmaxf(acc[h2][jn][3]*g1 + b1v, 0.f));
            }
        }
    } else {
        // bn2 + residual + relu, transposed into g_t via smem chunks of 32 co
        float* tb = sm;   // 128*33 = 4224 floats <= 15616
        for (int cc = 0; cc < 2; cc++){
            __syncthreads();
            if (warp_m == cc){
                #pragma unroll
                for (int h2 = 0; h2 < 2; h2++){
                    int co2 = h2*16 + gid;             // 0..31 within chunk
                    int co  = co0 + cc*32 + co2;
                    float g0 = bg[co],   b0v = bb[co];
                    float g1 = bg[co+8], b1v = bb[co+8];
                    const float* res0 = x + ((long)bi*256 + co)*256;
                    const float* res1 = x + ((long)bi*256 + co + 8)*256;
                    #pragma unroll
                    for (int jn = 0; jn < 4; jn++){
                        int col = n0 + warp_n*32 + jn*8 + tig*2;
                        int cl  = warp_n*32 + jn*8 + tig*2;   // 0..127
                        tb[cl*33 + co2]       = fmaxf(acc[h2][jn][0]*g0 + b0v + res0[col], 0.f);
                        tb[(cl+1)*33 + co2]   = fmaxf(acc[h2][jn][1]*g0 + b0v + res0[col+1], 0.f);
                        tb[cl*33 + co2 + 8]   = fmaxf(acc[h2][jn][2]*g1 + b1v + res1[col], 0.f);
                        tb[(cl+1)*33 + co2+8] = fmaxf(acc[h2][jn][3]*g1 + b1v + res1[col+1], 0.f);
                    }
                }
            }
            __syncthreads();
            for (int idx = tid; idx < 4096; idx += 256){
                int p = idx >> 5, c = idx & 31;
                g_t[((long)bi*256 + n0 + p)*256 + co0 + cc*32 + c] = tb[p*33 + c];
            }
        }
    }
}

// ============ LN_attn + q-proj, 32 rows/block (blocks 0..255); e0 (blocks 256..287) ============
__global__ __launch_bounds__(256)
void lnq_mma(const float* __restrict__ lg, const float* __restrict__ lb,
             const float* __restrict__ wq, const float* __restrict__ wqe){
    extern __shared__ float xn[];      // [k=256][m=33]
    __shared__ float gb[512];
    int tid = threadIdx.x, lane = tid&31, wid = tid>>5;
    int gid = lane>>2, tig = lane&3;

    if (blockIdx.x >= 256){
        __shared__ float xr[256];
        __shared__ float part[256];
        __shared__ float q0[64];
        __shared__ float red[16];
        int b = blockIdx.x - 256;
        int wp = wid, l = lane;
        float v = g_t[((long)b*256)*256 + tid];
        float s = wsum(v), sq = wsum(v*v);
        if (l == 0){ red[wp] = s; red[8+wp] = sq; }
        __syncthreads();
        float st = 0.f, sqt = 0.f;
        #pragma unroll
        for (int i = 0; i < 8; i++){ st += red[i]; sqt += red[8+i]; }
        float mean = st*(1.f/256.f);
        float rstd = rsqrtf(sqt*(1.f/256.f) - mean*mean + EPS_);
        xr[tid] = (v-mean)*rstd*lg[tid] + lb[tid];
        __syncthreads();
        int d = tid & 63, quarter = tid >> 6;
        float a = 0.f;
        #pragma unroll 8
        for (int j = quarter*64; j < quarter*64 + 64; j++)
            a = fmaf(xr[j], wq[j*64 + d], a);
        part[quarter*64 + d] = a;
        __syncthreads();
        if (tid < 64) q0[tid] = part[tid] + part[64+tid] + part[128+tid] + part[192+tid];
        __syncthreads();
        float a0=0.f, a1=0.f, a2=0.f, a3=0.f;
        #pragma unroll
        for (int dd = 0; dd < 64; dd += 4){
            a0 = fmaf(q0[dd+0], wqe[(dd+0)*256 + tid], a0);
            a1 = fmaf(q0[dd+1], wqe[(dd+1)*256 + tid], a1);
            a2 = fmaf(q0[dd+2], wqe[(dd+2)*256 + tid], a2);
            a3 = fmaf(q0[dd+3], wqe[(dd+3)*256 + tid], a3);
        }
        g_e0[b*256 + tid] = (a0+a1)+(a2+a3);
        return;
    }

    int r0 = blockIdx.x*32;
    gb[tid] = lg[tid]; gb[256+tid] = lb[tid];
    __syncthreads();
    int l = lane;
    for (int rr = 0; rr < 4; rr++){
        int r = wid*4 + rr;
        const float* row = g_t + (long)(r0+r)*256;
        float vv[8], s = 0.f, sq = 0.f;
        #pragma unroll
        for (int e = 0; e < 8; e++){ float v = row[l+32*e]; vv[e]=v; s+=v; sq+=v*v; }
        s = wsum(s); sq = wsum(sq);
        float mean = s*(1.f/256.f);
        float rstd = rsqrtf(sq*(1.f/256.f) - mean*mean + EPS_);
        #pragma unroll
        for (int e = 0; e < 8; e++){
            int j = l+32*e;
            xn[j*33 + r] = to_tf32((vv[e]-mean)*rstd*gb[j] + gb[256+j]);
        }
    }
    __syncthreads();
    int warp_m = wid & 1, warp_n = wid >> 1;
    int m0 = warp_m*16, n0w = warp_n*16;
    float acc[2][4];
    #pragma unroll
    for (int j = 0; j < 2; j++)
      #pragma unroll
      for (int i = 0; i < 4; i++) acc[j][i] = 0.f;
    for (int ks = 0; ks < 32; ks++){
        int k0 = ks*8;
        uint32_t a[4];
        a[0] = __float_as_uint(xn[(k0+tig)*33 + m0+gid]);
        a[1] = __float_as_uint(xn[(k0+tig)*33 + m0+gid+8]);
        a[2] = __float_as_uint(xn[(k0+tig+4)*33 + m0+gid]);
        a[3] = __float_as_uint(xn[(k0+tig+4)*33 + m0+gid+8]);
        #pragma unroll
        for (int jn = 0; jn < 2; jn++){
            int col = n0w + jn*8 + gid;
            uint32_t b0 = __float_as_uint(to_tf32(wq[(k0+tig)*64 + col]));
            uint32_t b1 = __float_as_uint(to_tf32(wq[(k0+tig+4)*64 + col]));
            mma8(acc[jn], a, b0, b1);
        }
    }
    #pragma unroll
    for (int jn = 0; jn < 2; jn++){
        int c = n0w + jn*8 + tig*2;
        #pragma unroll
        for (int half = 0; half < 2; half++){
            int r = r0 + m0 + gid + half*8;
            *(float2*)(g_q + (long)r*64 + c) =
                make_float2(acc[jn][half*2+0], acc[jn][half*2+1]);
        }
    }
}

// ============ score via tf32 mma, 64 rows/block, fused histogram ============
__global__ __launch_bounds__(256)
void score_mma_kernel(const float* __restrict__ rdata,
                      const float* __restrict__ gc, const float* __restrict__ bc){
    extern __shared__ float smd[];
    float* cs  = smd;                 // [k=256][m=65]
    float* e0T = smd + 16640;         // [k=256][b=33]
    float* s2s = smd + 25088;         // [64]
    float* sc  = smd + 25152;         // [64][33]
    __shared__ float gs[DD], bs[DD];
    int tid = threadIdx.x;
    for (int idx = tid; idx < 8192; idx += 256){
        int b = idx >> 8, k = idx & 255;
        e0T[k*33 + b] = to_tf32(g_e0[idx]);
    }
    for (int idx = tid; idx < DD; idx += 256){ gs[idx] = gc[idx]; bs[idx] = bc[idx]; }
    __syncthreads();
    int i0 = blockIdx.x*64;
    int wp = tid>>5, l = tid&31;
    for (int rr = 0; rr < 8; rr++){
        int lrow = wp*8 + rr;
        long i = i0 + lrow;
        if (i >= NBUF) i = NBUF - 1;
        const float* row = rdata + i*DD;
        float r[8], s = 0.f, sq = 0.f;
        #pragma unroll
        for (int e = 0; e < 8; e++){ float vv = row[l+32*e]; r[e]=vv; s+=vv; sq+=vv*vv; }
        float v8 = (l < 10) ? row[256+l] : 0.f;
        s += v8; sq += v8*v8;
        s = wsum(s); sq = wsum(sq);
        float mean = s*(1.f/266.f);
        float rstd = rsqrtf(sq*(1.f/266.f) - mean*mean + EPS_);
        float s2p = 0.f;
        #pragma unroll
        for (int e = 0; e < 8; e++){
            int j = l+32*e;
            float cv = (r[e]-mean)*rstd*gs[j] + bs[j];
            cs[j*65 + lrow] = to_tf32(cv);
            s2p += cv*cv;
        }
        float s2 = wsum(s2p);
        if (l == 0) s2s[lrow] = s2;
    }
    __syncthreads();
    int gid = l >> 2, tig = l & 3;
    int m0 = (wp & 3)*16, nc = (wp >> 2)*16;
    float acc[2][4];
    #pragma unroll
    for (int j = 0; j < 2; j++)
      #pragma unroll
      for (int i = 0; i < 4; i++) acc[j][i] = 0.f;
    #pragma unroll 4
    for (int k0 = 0; k0 < 256; k0 += 8){
        uint32_t a[4];
        a[0] = __float_as_uint(cs[(k0+tig)*65 + m0+gid]);
        a[1] = __float_as_uint(cs[(k0+tig)*65 + m0+gid+8]);
        a[2] = __float_as_uint(cs[(k0+tig+4)*65 + m0+gid]);
        a[3] = __float_as_uint(cs[(k0+tig+4)*65 + m0+gid+8]);
        #pragma unroll
        for (int jnn = 0; jnn < 2; jnn++){
            uint32_t b0 = __float_as_uint(e0T[(k0+tig)*33 + nc + jnn*8 + gid]);
            uint32_t b1 = __float_as_uint(e0T[(k0+tig+4)*33 + nc + jnn*8 + gid]);
            mma8(acc[jnn], a, b0, b1);
        }
    }
    #pragma unroll
    for (int jnn = 0; jnn < 2; jnn++){
        #pragma unroll
        for (int half = 0; half < 2; half++){
            int rowm = m0 + gid + half*8;
            float s2v = s2s[rowm];
            int c0 = nc + jnn*8 + tig*2;
            sc[rowm*33 + c0]   = s2v - 2.f*acc[jnn][half*2+0];
            sc[rowm*33 + c0+1] = s2v - 2.f*acc[jnn][half*2+1];
        }
    }
    __syncthreads();
    for (int idx = tid; idx < 2048; idx += 256){
        int b = idx >> 6, rr2 = idx & 63;
        if (i0 + rr2 < NBUF){
            float v = sc[rr2*33 + b];
            g_scores[(long)b*NBUF + i0 + rr2] = v;
            atomicAdd(&g_hist[b*65536 + (fkey(v) >> 16)], 1u);
        }
    }
}

__global__ __launch_bounds__(256)
void scan_kernel(){
    __shared__ unsigned ps[256];
    int b = blockIdx.x, t = threadIdx.x;
    const uint4* h4 = (const uint4*)(g_hist + b*65536 + t*256);
    unsigned sum = 0;
    #pragma unroll 8
    for (int i = 0; i < 64; i++){
        uint4 u = h4[i];
        sum += u.x + u.y + u.z + u.w;
    }
    ps[t] = sum;
    __syncthreads();
    for (int st = 1; st < 256; st <<= 1){
        unsigned v = (t >= (unsigned)st) ? ps[t-st] : 0u;
        __syncthreads();
        ps[t] += v;
        __syncthreads();
    }
    unsigned prev = (t == 0) ? 0u : ps[t-1];
    if (prev < 64u && ps[t] >= 64u){
        const unsigned* h = g_hist + b*65536;
        unsigned c = prev, T = t*256;
        for (int i = 0; i < 256; i++){
            c += h[t*256 + i];
            if (c >= 64u){ T = t*256 + i; break; }
        }
        g_thresh[b] = T;
    }
}
__global__ void compact_kernel(){
    int b = blockIdx.y;
    unsigned T = g_thresh[b];
    const float* s = g_scores + (long)b*NBUF;
    int base = blockIdx.x*8192;
    #pragma unroll
    for (int k = 0; k < 8; k++){
        int i = base + k*1024 + threadIdx.x;
        if (i < NBUF){
            float v = s[i];
            if ((fkey(v) >> 16) <= T){
                int pos = atomicAdd(&g_cc[b], 1);
                if (pos < CAP_){ g_ci[b*CAP_+pos] = i; }
            }
        }
    }
}
__global__ __launch_bounds__(256)
void rescore_refine(const float* __restrict__ rdata,
                    const float* __restrict__ gc, const float* __restrict__ bc){
    int b = blockIdx.x, tid = threadIdx.x;
    int wp = tid>>5, l = tid&31;
    __shared__ float e0s[256];
    __shared__ float gs[DD], bs[DD];
    e0s[tid] = g_e0[b*256 + tid];
    for (int i = tid; i < DD; i += 256){ gs[i] = gc[i]; bs[i] = bc[i]; }
    __syncthreads();
    int n = min(g_cc[b], CAP_);
    for (int c = wp; c < n; c += 8){
        long row = g_ci[b*CAP_ + c];
        const float* r = rdata + row*DD;
        float v[8], s = 0.f, sq = 0.f;
        #pragma unroll
        for (int e = 0; e < 8; e++){ float vv = r[l+32*e]; v[e]=vv; s+=vv; sq+=vv*vv; }
        float v8 = (l < 10) ? r[256+l] : 0.f;
        s += v8; sq += v8*v8;
        s = wsum(s); sq = wsum(sq);
        float mean = s*(1.f/266.f);
        float rstd = rsqrtf(sq*(1.f/266.f) - mean*mean + EPS_);
        float s2p = 0.f, dotp = 0.f;
        #pragma unroll
        for (int e = 0; e < 8; e++){
            int j = l+32*e;
            float cv = (v[e]-mean)*rstd*gs[j] + bs[j];
            s2p += cv*cv;
            dotp = fmaf(cv, e0s[j], dotp);
        }
        float s2 = wsum(s2p);
        float dot = wsum(dotp);
        if (l == 0) g_cv[b*CAP_ + c] = s2 - 2.f*dot;
    }
    __syncthreads();
    __shared__ float sv[256]; __shared__ int si[256];
    __shared__ float last_v; __shared__ int last_i;
    if (tid == 0){ last_v = -INFINITY; last_i = -1; }
    __syncthreads();
    const float* cv = g_cv + b*CAP_;
    const int*   ci = g_ci + b*CAP_;
    for (int r = 0; r < TOPK_; r++){
        float lv = last_v; int li = last_i;
        float bv = INFINITY; int bi = 0x7fffffff;
        for (int j = tid; j < n; j += 256){
            float v = cv[j]; int gi = ci[j];
            bool valid = (v > lv) || (v == lv && gi > li);
            if (valid && (v < bv || (v == bv && gi < bi))){ bv = v; bi = gi; }
        }
        sv[tid] = bv; si[tid] = bi;
        __syncthreads();
        for (int st = 128; st > 0; st >>= 1){
            if (tid < st){
                float ov = sv[tid+st]; int oi = si[tid+st];
                if (ov < sv[tid] || (ov == sv[tid] && oi < si[tid])){ sv[tid]=ov; si[tid]=oi; }
            }
            __syncthreads();
        }
        if (tid == 0){ g_idx[b*TOPK_+r] = si[0]; last_v = sv[0]; last_i = si[0]; }
        __syncthreads();
    }
}

__global__ __launch_bounds__(64)
void gather_kv_kernel(const float* __restrict__ rdata,
                      const float* __restrict__ gc, const float* __restrict__ bc,
                      const float* __restrict__ wk, const float* __restrict__ wv){
    int rid = blockIdx.x, tid = threadIdx.x;
    long row = g_idx[rid];
    const float* r = rdata + row*DD;
    __shared__ float c_sh[DD];
    __shared__ float r1[64], r2[64];
    float vals[5]; float s = 0.f, sq = 0.f;
    #pragma unroll
    for (int e = 0; e < 5; e++){
        int j = tid + 64*e;
        float v = (j < DD) ? r[j] : 0.f;
        vals[e] = v; s += v; sq += v*v;
    }
    r1[tid] = s; r2[tid] = sq;
    __syncthreads();
    for (int st = 32; st > 0; st >>= 1){
        if (tid < st){ r1[tid] += r1[tid+st]; r2[tid] += r2[tid+st]; }
        __syncthreads();
    }
    float mean = r1[0]*(1.f/266.f);
    float rstd = rsqrtf(r2[0]*(1.f/266.f) - mean*mean + EPS_);
    #pragma unroll
    for (int e = 0; e < 5; e++){
        int j = tid + 64*e;
        if (j < DD) c_sh[j] = (vals[e]-mean)*rstd*gc[j] + bc[j];
    }
    __syncthreads();
    float ka = 0.f;
    #pragma unroll 4
    for (int j = 0; j < 256; j++) ka = fmaf(c_sh[j], wk[j*64+tid], ka);
    float va = 0.f;
    #pragma unroll
    for (int j = 0; j < 10; j++) va = fmaf(c_sh[256+j], wv[j*64+tid], va);
    g_k[(long)rid*64 + tid] = ka;
    g_v[(long)rid*64 + tid] = va;
}

// attention: grid (32 x 4), 64 threads, 1 token/thread
__global__ __launch_bounds__(64)
void attn_kernel(){
    int b = blockIdx.x, qq = blockIdx.y;
    int tid = threadIdx.x;
    __shared__ float k_sh[TOPK_*64];
    __shared__ float v_sh[TOPK_*64];
    for (int idx = tid; idx < TOPK_*64; idx += 64){
        k_sh[idx] = g_k[(long)b*TOPK_*64 + idx];
        v_sh[idx] = g_v[(long)b*TOPK_*64 + idx];
    }
    __syncthreads();
    int n = qq*64 + tid;
    const float4* qr = (const float4*)(g_q + ((long)b*HWP + n)*64);
    float4 q4[16];
    #pragma unroll
    for (int i = 0; i < 16; i++) q4[i] = qr[i];
    float sim[32]; float mx = -INFINITY;
    #pragma unroll
    for (int j = 0; j < 32; j++){
        const float4* k4 = (const float4*)&k_sh[j*64];
        float a = 0.f;
        #pragma unroll
        for (int i = 0; i < 16; i++){
            float4 kv = k4[i];
            a += q4[i].x*kv.x + q4[i].y*kv.y + q4[i].z*kv.z + q4[i].w*kv.w;
        }
        a *= 0.125f;
        sim[j] = a; mx = fmaxf(mx, a);
    }
    float den = 0.f;
    #pragma unroll
    for (int j = 0; j < 32; j++){ sim[j] = expf(sim[j]-mx); den += sim[j]; }
    float inv = 1.f/den;
    float o[64];
    #pragma unroll
    for (int i = 0; i < 64; i++) o[i] = 0.f;
    #pragma unroll
    for (int j = 0; j < 32; j++){
        float a = sim[j]*inv;
        #pragma unroll
        for (int i = 0; i < 64; i++) o[i] = fmaf(a, v_sh[j*64+i], o[i]);
    }
    float4* orow = (float4*)(g_o + ((long)b*HWP + n)*64);
    #pragma unroll
    for (int i = 0; i < 16; i++)
        orow[i] = make_float4(o[4*i], o[4*i+1], o[4*i+2], o[4*i+3]);
}

// ============ wo-proj (tf32 mma) + residual + LN_ff, 32 rows/block ============
__global__ __launch_bounds__(256)
void woln_mma(const float* __restrict__ wo, const float* __restrict__ bo,
              const float* __restrict__ gf, const float* __restrict__ bf){
    extern __shared__ float smw[];
    float* os = smw;              // [k=64][m=33]
    float* ts = smw + 64*33;      // [32][257]
    __shared__ float gb[512];
    int tid = threadIdx.x, lane = tid&31, wid = tid>>5;
    int gid = lane>>2, tig = lane&3;
    int r0 = blockIdx.x*32;
    gb[tid] = gf[tid]; gb[256+tid] = bf[tid];
    for (int idx = tid; idx < 2048; idx += 256){
        int m = idx >> 6, d = idx & 63;
        os[d*33 + m] = to_tf32(g_o[(long)(r0+m)*64 + d]);
    }
    __syncthreads();
    int warp_m = wid & 1, warp_n = wid >> 1;
    int m0 = warp_m*16, n0w = warp_n*64;
    float acc[8][4];
    #pragma unroll
    for (int j = 0; j < 8; j++)
      #pragma unroll
      for (int i = 0; i < 4; i++) acc[j][i] = 0.f;
    for (int ks = 0; ks < 8; ks++){
        int k0 = ks*8;
        uint32_t a[4];
        a[0] = __float_as_uint(os[(k0+tig)*33 + m0+gid]);
        a[1] = __float_as_uint(os[(k0+tig)*33 + m0+gid+8]);
        a[2] = __float_as_uint(os[(k0+tig+4)*33 + m0+gid]);
        a[3] = __float_as_uint(os[(k0+tig+4)*33 + m0+gid+8]);
        #pragma unroll
        for (int jn = 0; jn < 8; jn++){
            int col = n0w + jn*8 + gid;
            uint32_t b0 = __float_as_uint(to_tf32(wo[(k0+tig)*256 + col]));
            uint32_t b1 = __float_as_uint(to_tf32(wo[(k0+tig+4)*256 + col]));
            mma8(acc[jn], a, b0, b1);
        }
    }
    #pragma unroll
    for (int jn = 0; jn < 8; jn++){
        int c = n0w + jn*8 + tig*2;
        float bc0 = bo[c], bc1 = bo[c+1];
        #pragma unroll
        for (int half = 0; half < 2; half++){
            int r = m0 + gid + half*8;
            float2 res = *(const float2*)(g_t + (long)(r0+r)*256 + c);
            float v0 = acc[jn][half*2+0] + bc0 + res.x;
            float v1 = acc[jn][half*2+1] + bc1 + res.y;
            *(float2*)(g_t + (long)(r0+r)*256 + c) = make_float2(v0, v1);
            ts[r*257 + c] = v0;
            ts[r*257 + c + 1] = v1;
        }
    }
    __syncthreads();
    int l = lane;
    for (int rr = 0; rr < 4; rr++){
        int r = wid*4 + rr;
        float s = 0.f, sq = 0.f;
        float vv[8];
        #pragma unroll
        for (int e = 0; e < 8; e++){ float v = ts[r*257 + l+32*e]; vv[e]=v; s += v; sq += v*v; }
        s = wsum(s); sq = wsum(sq);
        float mean = s*(1.f/256.f);
        float rstd = rsqrtf(sq*(1.f/256.f) - mean*mean + EPS_);
        #pragma unroll
        for (int e = 0; e < 8; e++){
            int j = l+32*e;
            g_lnf[(long)(r0+r)*256 + j] = (vv[e]-mean)*rstd*gb[j] + gb[256+j];
        }
    }
}

// FFN GEMM1
__global__ __launch_bounds__(256)
void ffn1_mma(const float* __restrict__ w1, const float* __restrict__ b1){
    __shared__ float As2[2][16][73];
    __shared__ float Bs[2][16][136];
    int tid = threadIdx.x, lane = tid&31, wid = tid>>5;
    int gid = lane>>2, tig = lane&3;
    int warp_m = wid&3, warp_n = wid>>2;
    int r0 = blockIdx.y*64, cn0 = blockIdx.x*64;

    float acc[8][4];
    #pragma unroll
    for (int j = 0; j < 8; j++)
      #pragma unroll
      for (int i = 0; i < 4; i++) acc[j][i] = 0.f;

    int am = tid>>2, akq = tid&3;
    auto stage = [&](int kc){
        int bf = kc&1, k0 = kc*16;
        float4 av = *(const float4*)(g_lnf + (long)(r0+am)*256 + k0 + akq*4);
        As2[bf][akq*4+0][am] = to_tf32(av.x);
        As2[bf][akq*4+1][am] = to_tf32(av.y);
        As2[bf][akq*4+2][am] = to_tf32(av.z);
        As2[bf][akq*4+3][am] = to_tf32(av.w);
        #pragma unroll
        for (int rep = 0; rep < 8; rep++){
            int linear = rep*256 + tid;
            int kr = linear>>7, c = linear&127;
            int src = (c < 64) ? (cn0 + c) : (256 + cn0 + c - 64);
            Bs[bf][kr][c] = to_tf32(w1[(long)(k0+kr)*512 + src]);
        }
    };
    stage(0);
    __syncthreads();
    int m0 = warp_m*16;
    for (int kc = 0; kc < 16; kc++){
        if (kc < 15) stage(kc+1);
        int bf = kc&1;
        #pragma unroll
        for (int ks = 0; ks < 2; ks++){
            uint32_t a[4];
            a[0] = __float_as_uint(As2[bf][ks*8+tig][m0+gid]);
            a[1] = __float_as_uint(As2[bf][ks*8+tig][m0+gid+8]);
            a[2] = __float_as_uint(As2[bf][ks*8+tig+4][m0+gid]);
            a[3] = __float_as_uint(As2[bf][ks*8+tig+4][m0+gid+8]);
            #pragma unroll
            for (int jn = 0; jn < 8; jn++){
                int col = (jn < 4) ? (warp_n*32 + jn*8 + gid)
                                   : (64 + warp_n*32 + (jn-4)*8 + gid);
                uint32_t b0 = __float_as_uint(Bs[bf][ks*8+tig][col]);
                uint32_t b1v = __float_as_uint(Bs[bf][ks*8+tig+4][col]);
                mma8(acc[jn], a, b0, b1v);
            }
        }
        __syncthreads();
    }
    #pragma unroll
    for (int jn = 0; jn < 4; jn++){
        int c = cn0 + warp_n*32 + jn*8 + tig*2;
        float ba0 = b1[c], ba1 = b1[c+1];
        float bg0 = b1[256+c], bg1 = b1[256+c+1];
        #pragma unroll
        for (int half = 0; half < 2; half++){
            int r = r0 + warp_m*16 + gid + half*8;
            float ha0 = acc[jn][half*2+0] + ba0;
            float ha1 = acc[jn][half*2+1] + ba1;
            float hg0 = acc[jn+4][half*2+0] + bg0;
            float hg1 = acc[jn+4][half*2+1] + bg1;
            *(float2*)(g_out1 + (long)r*256 + c) =
                make_float2(ha0*gelu_exact(hg0), ha1*gelu_exact(hg1));
        }
    }
}

// FFN GEMM2
__global__ __launch_bounds__(256)
void ffn2_mma(const float* __restrict__ w2, const float* __restrict__ b2,
              float* __restrict__ out){
    __shared__ float As2[2][16][73];
    __shared__ float Bs[2][16][72];
    int tid = threadIdx.x, lane = tid&31, wid = tid>>5;
    int gid = lane>>2, tig = lane&3;
    int warp_m = wid&3, warp_n = wid>>2;
    int r0 = blockIdx.y*64, cn0 = blockIdx.x*64;

    float acc[4][4];
    #pragma unroll
    for (int j = 0; j < 4; j++)
      #pragma unroll
      for (int i = 0; i < 4; i++) acc[j][i] = 0.f;

    int am = tid>>2, akq = tid&3;
    auto stage = [&](int kc){
        int bf = kc&1, k0 = kc*16;
        float4 av = *(const float4*)(g_out1 + (long)(r0+am)*256 + k0 + akq*4);
        As2[bf][akq*4+0][am] = to_tf32(av.x);
        As2[bf][akq*4+1][am] = to_tf32(av.y);
        As2[bf][akq*4+2][am] = to_tf32(av.z);
        As2[bf][akq*4+3][am] = to_tf32(av.w);
        #pragma unroll
        for (int rep = 0; rep < 4; rep++){
            int linear = rep*256 + tid;
            int kr = linear>>6, c = linear&63;
            Bs[bf][kr][c] = to_tf32(w2[(long)(k0+kr)*256 + cn0 + c]);
        }
    };
    stage(0);
    __syncthreads();
    int m0 = warp_m*16;
    for (int kc = 0; kc < 16; kc++){
        if (kc < 15) stage(kc+1);
        int bf = kc&1;
        #pragma unroll
        for (int ks = 0; ks < 2; ks++){
            uint32_t a[4];
            a[0] = __float_as_uint(As2[bf][ks*8+tig][m0+gid]);
            a[1] = __float_as_uint(As2[bf][ks*8+tig][m0+gid+8]);
            a[2] = __float_as_uint(As2[bf][ks*8+tig+4][m0+gid]);
            a[3] = __float_as_uint(As2[bf][ks*8+tig+4][m0+gid+8]);
            #pragma unroll
            for (int jn = 0; jn < 4; jn++){
                int col = warp_n*32 + jn*8 + gid;
                uint32_t b0 = __float_as_uint(Bs[bf][ks*8+tig][col]);
                uint32_t b1v = __float_as_uint(Bs[bf][ks*8+tig+4][col]);
                mma8(acc[jn], a, b0, b1v);
            }
        }
        __syncthreads();
    }
    #pragma unroll
    for (int jn = 0; jn < 4; jn++){
        int c = cn0 + warp_n*32 + jn*8 + tig*2;
        float bc0 = b2[c], bc1 = b2[c+1];
        #pragma unroll
        for (int half = 0; half < 2; half++){
            int r = r0 + warp_m*16 + gid + half*8;
            float2 res = *(const float2*)(g_t + (long)r*256 + c);
            float v0 = acc[jn][half*2+0] + bc0 + res.x;
            float v1 = acc[jn][half*2+1] + bc1 + res.y;
            int b = r >> 8, p = r & 255;
            out[((long)b*256 + c)*256 + p]   = v0;
            out[((long)b*256 + c+1)*256 + p] = v1;
        }
    }
}

extern "C" void kernel_launch(void* const* d_in, const int* in_sizes, int n_in,
                              void* d_out, int out_size) {
    const float* x       = (const float*)d_in[0];
    const float* conv1_w = (const float*)d_in[1];
    const float* conv2_w = (const float*)d_in[2];
    const float* bn1_g   = (const float*)d_in[3];
    const float* bn1_b   = (const float*)d_in[4];
    const float* bn2_g   = (const float*)d_in[5];
    const float* bn2_b   = (const float*)d_in[6];
    const float* rdata   = (const float*)d_in[7];
    const float* ln_attn_g = (const float*)d_in[8];
    const float* ln_attn_b = (const float*)d_in[9];
    const float* ln_ctx_g  = (const float*)d_in[10];
    const float* ln_ctx_b  = (const float*)d_in[11];
    const float* wq  = (const float*)d_in[12];
    const float* wk  = (const float*)d_in[13];
    const float* wv  = (const float*)d_in[14];
    const float* wqe = (const float*)d_in[15];
    const float* wo  = (const float*)d_in[16];
    const float* bo  = (const float*)d_in[17];
    const float* ln_ff_g = (const float*)d_in[18];
    const float* ln_ff_b = (const float*)d_in[19];
    const float* w1  = (const float*)d_in[20];
    const float* b1  = (const float*)d_in[21];
    const float* w2  = (const float*)d_in[22];
    const float* b2  = (const float*)d_in[23];
    float* out = (float*)d_out;

    const int conv_smem  = (2*AS_BUF + 2*XS_BUF) * 4;   // 62464 B
    const int score_smem = (25152 + 64*33) * 4;
    const int lnq_smem   = 256*33*4;
    const int woln_smem  = (64*33 + 32*257)*4;
    cudaFuncSetAttribute(conv_mma_kernel<1>, cudaFuncAttributeMaxDynamicSharedMemorySize, conv_smem);
    cudaFuncSetAttribute(conv_mma_kernel<2>, cudaFuncAttributeMaxDynamicSharedMemorySize, conv_smem);
    cudaFuncSetAttribute(score_mma_kernel, cudaFuncAttributeMaxDynamicSharedMemorySize, score_smem);
    cudaFuncSetAttribute(lnq_mma, cudaFuncAttributeMaxDynamicSharedMemorySize, lnq_smem);
    cudaFuncSetAttribute(woln_mma, cudaFuncAttributeMaxDynamicSharedMemorySize, woln_smem);

    wtrans2_kernel<<<512, 256>>>(conv1_w, conv2_w);
    conv_mma_kernel<1><<<256, 256, conv_smem>>>(x, bn1_g, bn1_b);
    conv_mma_kernel<2><<<256, 256, conv_smem>>>(x, bn2_g, bn2_b);
    lnq_mma<<<288, 256, lnq_smem>>>(ln_attn_g, ln_attn_b, wq, wqe);
    score_mma_kernel<<<1563, 256, score_smem>>>(rdata, ln_ctx_g, ln_ctx_b);
    scan_kernel<<<32, 256>>>();
    compact_kernel<<<dim3(13,32), 1024>>>();
    rescore_refine<<<32, 256>>>(rdata, ln_ctx_g, ln_ctx_b);
    gather_kv_kernel<<<1024, 64>>>(rdata, ln_ctx_g, ln_ctx_b, wk, wv);
    attn_kernel<<<dim3(32,4), 64>>>();
    woln_mma<<<256, 256, woln_smem>>>(wo, bo, ln_ff_g, ln_ff_b);
    ffn1_mma<<<dim3(4,128), 256>>>(w1, b1);
    ffn2_mma<<<dim3(4,128), 256>>>(w2, b2, out);
}

// round 15
// speedup vs baseline: 1.0429x; 1.0429x over previous
#include <cuda_runtime.h>
#include <math.h>
#include <stdint.h>

#define B_    32
#define C_    256
#define HWP   256
#define NROWS 8192
#define NBUF  100000
#define DD    266
#define TOPK_ 32
#define EPS_  1e-5f
#define CAP_  8192

__device__ __align__(16) float g_out1[B_*C_*HWP];
__device__ __align__(16) float g_wt[9*256*256];
__device__ __align__(16) float g_wt2[9*256*256];
__device__ float g_t[NROWS*C_];
__device__ float g_q[NROWS*64];
__device__ float g_e0[B_*256];
__device__ __align__(16) float g_e0t[256*32];       // tf32 e0, k-major [k][b]
__device__ __align__(16) unsigned short g_skey[(long)B_*NBUF];
__device__ int   g_idx[B_*TOPK_];
__device__ float g_k[B_*TOPK_*64];
__device__ float g_v[B_*TOPK_*64];
__device__ float g_o[NROWS*64];
__device__ float g_lnf[NROWS*C_];
__device__ __align__(16) unsigned g_hist[32*65536];
__device__ unsigned g_thresh[32];
__device__ float g_cv[32*CAP_];
__device__ int   g_ci[32*CAP_];
__device__ int   g_cc[32];

__device__ __forceinline__ float wsum(float v){
    v += __shfl_xor_sync(0xffffffffu, v, 16);
    v += __shfl_xor_sync(0xffffffffu, v, 8);
    v += __shfl_xor_sync(0xffffffffu, v, 4);
    v += __shfl_xor_sync(0xffffffffu, v, 2);
    v += __shfl_xor_sync(0xffffffffu, v, 1);
    return v;
}
__device__ __forceinline__ float gelu_exact(float v){
    return 0.5f * v * (1.0f + erff(v * 0.7071067811865476f));
}
__device__ __forceinline__ float to_tf32(float x){
    uint32_t u;
    asm("cvt.rna.tf32.f32 %0, %1;" : "=r"(u) : "f"(x));
    return __uint_as_float(u);
}
__device__ __forceinline__ void mma8(float* c, const uint32_t* a, uint32_t b0, uint32_t b1){
    asm volatile("mma.sync.aligned.m16n8k8.row.col.f32.tf32.tf32.f32 "
        "{%0,%1,%2,%3},{%4,%5,%6,%7},{%8,%9},{%0,%1,%2,%3};"
        : "+f"(c[0]),"+f"(c[1]),"+f"(c[2]),"+f"(c[3])
        : "r"(a[0]),"r"(a[1]),"r"(a[2]),"r"(a[3]),"r"(b0),"r"(b1));
}
__device__ __forceinline__ unsigned fkey(float f){
    unsigned u = __float_as_uint(f);
    return (u & 0x80000000u) ? ~u : (u | 0x80000000u);
}
__device__ __forceinline__ void cp4(uint32_t s, const void* g){
    asm volatile("cp.async.ca.shared.global [%0], [%1], 4;" :: "r"(s), "l"(g));
}
__device__ __forceinline__ void cp8(uint32_t s, const void* g){
    asm volatile("cp.async.ca.shared.global [%0], [%1], 8;" :: "r"(s), "l"(g));
}
#define CP_COMMIT() asm volatile("cp.async.commit_group;")
template<int N>
__device__ __forceinline__ void cp_wait(){
    asm volatile("cp.async.wait_group %0;" :: "n"(N));
}

// ============ coalesced weight transpose + hist/cc zero ============
__global__ __launch_bounds__(256)
void wtrans2_kernel(const float* __restrict__ wa, const float* __restrict__ wb){
    __shared__ float tile[32][73];
    int bid = blockIdx.x;
    int which = bid >> 8;
    int t2 = bid & 255;
    int cob = t2 >> 5;
    int cib = t2 & 31;
    const float* w = which ? wb : wa;
    float* dst = which ? g_wt2 : g_wt;
    int tid = threadIdx.x;
    for (unsigned i = bid*256u + tid; i < 32u*65536u; i += 512u*256u) g_hist[i] = 0u;
    if (bid == 0 && tid < 32) g_cc[tid] = 0;
    for (int i = tid; i < 2304; i += 256){
        int co = i / 72, e = i % 72;
        tile[co][e] = to_tf32(w[(long)(cob*32+co)*2304 + cib*72 + e]);
    }
    __syncthreads();
    for (int i = tid; i < 2304; i += 256){
        int p = i >> 5, co = i & 31;
        int ci_l = p / 9, tap = p % 9;
        dst[((long)tap*256 + cib*8 + ci_l)*256 + cob*32 + co] = tile[co][ci_l*9+tap];
    }
}

// ============ conv (R13 shape): 128 blocks, 512 thr, cp.async staging ============
#define AS_BUF (9*8*136)
#define XS_BUF (8*328)
template<int WHICH>
__global__ __launch_bounds__(512,1)
void conv_mma_kernel(const float* __restrict__ x,
                     const float* __restrict__ bg, const float* __restrict__ bb){
    extern __shared__ float sm[];
    float* As = sm;
    float* Xs = sm + 2*AS_BUF;

    int tid  = threadIdx.x;
    int lane = tid & 31, wid = tid >> 5;
    int gid  = lane >> 2, tig = lane & 3;
    int warp_m = wid & 3, warp_n = wid >> 2;

    int bi  = blockIdx.x >> 2;
    int co0 = ((blockIdx.x >> 1) & 1) << 7;
    int n0  = (blockIdx.x & 1) << 7;

    const float* xin = (WHICH == 1) ? x : (const float*)g_out1;
    const float* wptr = (WHICH == 1) ? g_wt : g_wt2;

    for (int i = tid; i < 2*XS_BUF; i += 512) Xs[i] = 0.0f;

    float acc[2][4][4];
    #pragma unroll
    for (int h2 = 0; h2 < 2; h2++)
      #pragma unroll
      for (int jn = 0; jn < 4; jn++)
        #pragma unroll
        for (int i = 0; i < 4; i++) acc[h2][jn][i] = 0.0f;

    int bp[4];
    #pragma unroll
    for (int jn = 0; jn < 4; jn++){
        int p = n0 + warp_n*32 + jn*8 + gid;
        bp[jn] = (p >> 4)*18 + (p & 15);
    }

    int a_row = tid >> 6;
    int a_col = (tid & 63) << 1;
    int xp    = tid & 255;
    int xr0   = (tid >> 8) << 2;
    int pr    = ((xp >> 4) + 1)*18 + (xp & 15) + 1;

    uint32_t as_b = (uint32_t)__cvta_generic_to_shared(As);
    uint32_t xs_b = (uint32_t)__cvta_generic_to_shared(Xs);

    auto stage = [&](int cg){
        int bf = cg & 1;
        int ci0 = cg << 3;
        uint32_t ad = as_b + (uint32_t)(bf*AS_BUF + a_row*136 + a_col)*4u;
        const float* ws = wptr + ((ci0 + a_row) << 8) + co0 + a_col;
        #pragma unroll
        for (int tap = 0; tap < 9; tap++)
            cp8(ad + (uint32_t)tap*1088u*4u, ws + (tap << 16));
        const float* xb = xin + ((long)bi*256 + ci0 + xr0)*256 + xp;
        uint32_t xd = xs_b + (uint32_t)(bf*XS_BUF + xr0*328 + pr)*4u;
        #pragma unroll
        for (int cr = 0; cr < 4; cr++)
            cp4(xd + (uint32_t)cr*328u*4u, xb + cr*256);
    };

    __syncthreads();
    stage(0);
    CP_COMMIT();

    int mb = warp_m*32;
    for (int cg = 0; cg < 32; cg++){
        cp_wait<0>();
        __syncthreads();
        if (cg + 1 < 32){ stage(cg + 1); CP_COMMIT(); }
        int bf = cg & 1;
        const float* Xb = &Xs[bf*XS_BUF];
        #pragma unroll
        for (int tap = 0; tap < 9; tap++){
            int toff = (tap/3)*18 + (tap%3);
            const float* Ab = &As[bf*AS_BUF + tap*1088];
            uint32_t a[2][4];
            #pragma unroll
            for (int h2 = 0; h2 < 2; h2++){
                int m0 = mb + h2*16;
                a[h2][0] = __float_as_uint(Ab[tig*136 + m0 + gid]);
                a[h2][1] = __float_as_uint(Ab[tig*136 + m0 + gid + 8]);
                a[h2][2] = __float_as_uint(Ab[(tig+4)*136 + m0 + gid]);
                a[h2][3] = __float_as_uint(Ab[(tig+4)*136 + m0 + gid + 8]);
            }
            #pragma unroll
            for (int jn = 0; jn < 4; jn++){
                uint32_t b0 = __float_as_uint(Xb[tig*328 + bp[jn] + toff]);
                uint32_t b1 = __float_as_uint(Xb[(tig+4)*328 + bp[jn] + toff]);
                mma8(acc[0][jn], a[0], b0, b1);
                mma8(acc[1][jn], a[1], b0, b1);
            }
        }
    }

    if (WHICH == 1){
        #pragma unroll
        for (int h2 = 0; h2 < 2; h2++){
            int co = co0 + mb + h2*16 + gid;
            float g0 = bg[co],   b0v = bb[co];
            float g1 = bg[co+8], b1v = bb[co+8];
            float* o0 = g_out1 + ((long)bi*256 + co)*256;
            float* o1 = g_out1 + ((long)bi*256 + co + 8)*256;
            #pragma unroll
            for (int jn = 0; jn < 4; jn++){
                int col = n0 + warp_n*32 + jn*8 + tig*2;
                *(float2*)(o0 + col) = make_float2(
                    fmaxf(acc[h2][jn][0]*g0 + b0v, 0.f),
                    fmaxf(acc[h2][jn][1]*g0 + b0v, 0.f));
                *(float2*)(o1 + col) = make_float2(
                    fmaxf(acc[h2][jn][2]*g1 + b1v, 0.f),
                    fmaxf(acc[h2][jn][3]*g1 + b1v, 0.f));
            }
        }
    } else {
        float* tb = sm;
        for (int cc = 0; cc < 4; cc++){
            __syncthreads();
            if (warp_m == cc){
                #pragma unroll
                for (int h2 = 0; h2 < 2; h2++){
                    int co2 = h2*16 + gid;
                    int co  = co0 + cc*32 + co2;
                    float g0 = bg[co],   b0v = bb[co];
                    float g1 = bg[co+8], b1v = bb[co+8];
                    const float* res0 = x + ((long)bi*256 + co)*256;
                    const float* res1 = x + ((long)bi*256 + co + 8)*256;
                    #pragma unroll
                    for (int jn = 0; jn < 4; jn++){
                        int col = n0 + warp_n*32 + jn*8 + tig*2;
                        int cl  = warp_n*32 + jn*8 + tig*2;
                        tb[cl*33 + co2]       = fmaxf(acc[h2][jn][0]*g0 + b0v + res0[col], 0.f);
                        tb[(cl+1)*33 + co2]   = fmaxf(acc[h2][jn][1]*g0 + b0v + res0[col+1], 0.f);
                        tb[cl*33 + co2 + 8]   = fmaxf(acc[h2][jn][2]*g1 + b1v + res1[col], 0.f);
                        tb[(cl+1)*33 + co2+8] = fmaxf(acc[h2][jn][3]*g1 + b1v + res1[col+1], 0.f);
                    }
                }
            }
            __syncthreads();
            for (int idx = tid; idx < 4096; idx += 512){
                int p = idx >> 5, c = idx & 31;
                g_t[((long)bi*256 + n0 + p)*256 + co0 + cc*32 + c] = tb[p*33 + c];
            }
        }
    }
}

// ============ LN_attn + q-proj, 32 rows/block (blocks 0..255); e0 (blocks 256..287) ============
__global__ __launch_bounds__(256)
void lnq_mma(const float* __restrict__ lg, const float* __restrict__ lb,
             const float* __restrict__ wq, const float* __restrict__ wqe){
    extern __shared__ float xn[];      // [k=256][m=33]
    __shared__ float gb[512];
    int tid = threadIdx.x, lane = tid&31, wid = tid>>5;
    int gid = lane>>2, tig = lane&3;

    if (blockIdx.x >= 256){
        __shared__ float xr[256];
        __shared__ float part[256];
        __shared__ float q0[64];
        __shared__ float red[16];
        int b = blockIdx.x - 256;
        int wp = wid, l = lane;
        float v = g_t[((long)b*256)*256 + tid];
        float s = wsum(v), sq = wsum(v*v);
        if (l == 0){ red[wp] = s; red[8+wp] = sq; }
        __syncthreads();
        float st = 0.f, sqt = 0.f;
        #pragma unroll
        for (int i = 0; i < 8; i++){ st += red[i]; sqt += red[8+i]; }
        float mean = st*(1.f/256.f);
        float rstd = rsqrtf(sqt*(1.f/256.f) - mean*mean + EPS_);
        xr[tid] = (v-mean)*rstd*lg[tid] + lb[tid];
        __syncthreads();
        int d = tid & 63, quarter = tid >> 6;
        float a = 0.f;
        #pragma unroll 8
        for (int j = quarter*64; j < quarter*64 + 64; j++)
            a = fmaf(xr[j], wq[j*64 + d], a);
        part[quarter*64 + d] = a;
        __syncthreads();
        if (tid < 64) q0[tid] = part[tid] + part[64+tid] + part[128+tid] + part[192+tid];
        __syncthreads();
        float a0=0.f, a1=0.f, a2=0.f, a3=0.f;
        #pragma unroll
        for (int dd = 0; dd < 64; dd += 4){
            a0 = fmaf(q0[dd+0], wqe[(dd+0)*256 + tid], a0);
            a1 = fmaf(q0[dd+1], wqe[(dd+1)*256 + tid], a1);
            a2 = fmaf(q0[dd+2], wqe[(dd+2)*256 + tid], a2);
            a3 = fmaf(q0[dd+3], wqe[(dd+3)*256 + tid], a3);
        }
        float e0v = (a0+a1)+(a2+a3);
        g_e0[b*256 + tid] = e0v;
        g_e0t[tid*32 + b] = to_tf32(e0v);
        return;
    }

    int r0 = blockIdx.x*32;
    gb[tid] = lg[tid]; gb[256+tid] = lb[tid];
    __syncthreads();
    int l = lane;
    for (int rr = 0; rr < 4; rr++){
        int r = wid*4 + rr;
        const float* row = g_t + (long)(r0+r)*256;
        float vv[8], s = 0.f, sq = 0.f;
        #pragma unroll
        for (int e = 0; e < 8; e++){ float v = row[l+32*e]; vv[e]=v; s+=v; sq+=v*v; }
        s = wsum(s); sq = wsum(sq);
        float mean = s*(1.f/256.f);
        float rstd = rsqrtf(sq*(1.f/256.f) - mean*mean + EPS_);
        #pragma unroll
        for (int e = 0; e < 8; e++){
            int j = l+32*e;
            xn[j*33 + r] = to_tf32((vv[e]-mean)*rstd*gb[j] + gb[256+j]);
        }
    }
    __syncthreads();
    int warp_m = wid & 1, warp_n = wid >> 1;
    int m0 = warp_m*16, n0w = warp_n*16;
    float acc[2][4];
    #pragma unroll
    for (int j = 0; j < 2; j++)
      #pragma unroll
      for (int i = 0; i < 4; i++) acc[j][i] = 0.f;
    for (int ks = 0; ks < 32; ks++){
        int k0 = ks*8;
        uint32_t a[4];
        a[0] = __float_as_uint(xn[(k0+tig)*33 + m0+gid]);
        a[1] = __float_as_uint(xn[(k0+tig)*33 + m0+gid+8]);
        a[2] = __float_as_uint(xn[(k0+tig+4)*33 + m0+gid]);
        a[3] = __float_as_uint(xn[(k0+tig+4)*33 + m0+gid+8]);
        #pragma unroll
        for (int jn = 0; jn < 2; jn++){
            int col = n0w + jn*8 + gid;
            uint32_t b0 = __float_as_uint(to_tf32(wq[(k0+tig)*64 + col]));
            uint32_t b1 = __float_as_uint(to_tf32(wq[(k0+tig+4)*64 + col]));
            mma8(acc[jn], a, b0, b1);
        }
    }
    #pragma unroll
    for (int jn = 0; jn < 2; jn++){
        int c = n0w + jn*8 + tig*2;
        #pragma unroll
        for (int half = 0; half < 2; half++){
            int r = r0 + m0 + gid + half*8;
            *(float2*)(g_q + (long)r*64 + c) =
                make_float2(acc[jn][half*2+0], acc[jn][half*2+1]);
        }
    }
}

// ============ score: 32 rows/block, e0 B-frags from L1, 16-bit keys out ============
__global__ __launch_bounds__(256)
void score_mma_kernel(const float* __restrict__ rdata,
                      const float* __restrict__ gc, const float* __restrict__ bc){
    extern __shared__ float smd[];
    float* cs  = smd;                 // [k=256][m=33] 8448
    float* s2s = smd + 8448;          // [32]
    float* sc  = smd + 8480;          // [32][33] 1056
    __shared__ float gs[DD], bs[DD];
    int tid = threadIdx.x;
    for (int idx = tid; idx < DD; idx += 256){ gs[idx] = gc[idx]; bs[idx] = bc[idx]; }
    __syncthreads();
    int i0 = blockIdx.x*32;           // 3125*32 == NBUF exactly
    int wp = tid>>5, l = tid&31;
    for (int rr = 0; rr < 4; rr++){
        int lrow = wp*4 + rr;
        const float* row = rdata + (long)(i0+lrow)*DD;
        float r[8], s = 0.f, sq = 0.f;
        #pragma unroll
        for (int e = 0; e < 8; e++){ float vv = row[l+32*e]; r[e]=vv; s+=vv; sq+=vv*vv; }
        float v8 = (l < 10) ? row[256+l] : 0.f;
        s += v8; sq += v8*v8;
        s = wsum(s); sq = wsum(sq);
        float mean = s*(1.f/266.f);
        float rstd = rsqrtf(sq*(1.f/266.f) - mean*mean + EPS_);
        float s2p = 0.f;
        #pragma unroll
        for (int e = 0; e < 8; e++){
            int j = l+32*e;
            float cv = (r[e]-mean)*rstd*gs[j] + bs[j];
            cs[j*33 + lrow] = to_tf32(cv);
            s2p += cv*cv;
        }
        float s2 = wsum(s2p);
        if (l == 0) s2s[lrow] = s2;
    }
    __syncthreads();
    int gid = l >> 2, tig = l & 3;
    int m0 = (wp & 1)*16, nc = (wp >> 1)*8;   // 2m x 4n warps
    float acc[4] = {0.f,0.f,0.f,0.f};
    #pragma unroll 4
    for (int k0 = 0; k0 < 256; k0 += 8){
        uint32_t a[4];
        a[0] = __float_as_uint(cs[(k0+tig)*33 + m0+gid]);
        a[1] = __float_as_uint(cs[(k0+tig)*33 + m0+gid+8]);
        a[2] = __float_as_uint(cs[(k0+tig+4)*33 + m0+gid]);
        a[3] = __float_as_uint(cs[(k0+tig+4)*33 + m0+gid+8]);
        uint32_t b0 = __float_as_uint(g_e0t[(k0+tig)*32 + nc+gid]);
        uint32_t b1 = __float_as_uint(g_e0t[(k0+tig+4)*32 + nc+gid]);
        mma8(acc, a, b0, b1);
    }
    #pragma unroll
    for (int half = 0; half < 2; half++){
        int rowm = m0 + gid + half*8;
        float s2v = s2s[rowm];
        int c0 = nc + tig*2;
        sc[rowm*33 + c0]   = s2v - 2.f*acc[half*2+0];
        sc[rowm*33 + c0+1] = s2v - 2.f*acc[half*2+1];
    }
    __syncthreads();
    for (int idx = tid; idx < 1024; idx += 256){
        int b = idx>>5, rr2 = idx&31;
        float v = sc[rr2*33 + b];
        unsigned key = fkey(v) >> 16;
        g_skey[(long)b*NBUF + i0 + rr2] = (unsigned short)key;
        atomicAdd(&g_hist[b*65536 + key], 1u);
    }
}

__global__ __launch_bounds__(256)
void scan_kernel(){
    __shared__ unsigned ps[256];
    int b = blockIdx.x, t = threadIdx.x;
    const uint4* h4 = (const uint4*)(g_hist + b*65536 + t*256);
    unsigned sum = 0;
    #pragma unroll 8
    for (int i = 0; i < 64; i++){
        uint4 u = h4[i];
        sum += u.x + u.y + u.z + u.w;
    }
    ps[t] = sum;
    __syncthreads();
    for (int st = 1; st < 256; st <<= 1){
        unsigned v = (t >= (unsigned)st) ? ps[t-st] : 0u;
        __syncthreads();
        ps[t] += v;
        __syncthreads();
    }
    unsigned prev = (t == 0) ? 0u : ps[t-1];
    if (prev < 64u && ps[t] >= 64u){
        const unsigned* h = g_hist + b*65536;
        unsigned c = prev, T = t*256;
        for (int i = 0; i < 256; i++){
            c += h[t*256 + i];
            if (c >= 64u){ T = t*256 + i; break; }
        }
        g_thresh[b] = T;
    }
}
__global__ void compact_kernel(){
    int b = blockIdx.y;
    unsigned short T = (unsigned short)g_thresh[b];
    const unsigned short* s = g_skey + (long)b*NBUF;
    int base = blockIdx.x*8192;
    #pragma unroll
    for (int k = 0; k < 8; k++){
        int i = base + k*1024 + threadIdx.x;
        if (i < NBUF){
            if (s[i] <= T){
                int pos = atomicAdd(&g_cc[b], 1);
                if (pos < CAP_){ g_ci[b*CAP_+pos] = i; }
            }
        }
    }
}
__global__ __launch_bounds__(256)
void rescore_refine(const float* __restrict__ rdata,
                    const float* __restrict__ gc, const float* __restrict__ bc){
    int b = blockIdx.x, tid = threadIdx.x;
    int wp = tid>>5, l = tid&31;
    __shared__ float e0s[256];
    __shared__ float gs[DD], bs[DD];
    e0s[tid] = g_e0[b*256 + tid];
    for (int i = tid; i < DD; i += 256){ gs[i] = gc[i]; bs[i] = bc[i]; }
    __syncthreads();
    int n = min(g_cc[b], CAP_);
    for (int c = wp; c < n; c += 8){
        long row = g_ci[b*CAP_ + c];
        const float* r = rdata + row*DD;
        float v[8], s = 0.f, sq = 0.f;
        #pragma unroll
        for (int e = 0; e < 8; e++){ float vv = r[l+32*e]; v[e]=vv; s+=vv; sq+=vv*vv; }
        float v8 = (l < 10) ? r[256+l] : 0.f;
        s += v8; sq += v8*v8;
        s = wsum(s); sq = wsum(sq);
        float mean = s*(1.f/266.f);
        float rstd = rsqrtf(sq*(1.f/266.f) - mean*mean + EPS_);
        float s2p = 0.f, dotp = 0.f;
        #pragma unroll
        for (int e = 0; e < 8; e++){
            int j = l+32*e;
            float cv = (v[e]-mean)*rstd*gs[j] + bs[j];
            s2p += cv*cv;
            dotp = fmaf(cv, e0s[j], dotp);
        }
        float s2 = wsum(s2p);
        float dot = wsum(dotp);
        if (l == 0) g_cv[b*CAP_ + c] = s2 - 2.f*dot;
    }
    __syncthreads();
    __shared__ float sv[256]; __shared__ int si[256];
    __shared__ float last_v; __shared__ int last_i;
    if (tid == 0){ last_v = -INFINITY; last_i = -1; }
    __syncthreads();
    const float* cv = g_cv + b*CAP_;
    const int*   ci = g_ci + b*CAP_;
    for (int r = 0; r < TOPK_; r++){
        float lv = last_v; int li = last_i;
        float bv = INFINITY; int bi = 0x7fffffff;
        for (int j = tid; j < n; j += 256){
            float v = cv[j]; int gi = ci[j];
            bool valid = (v > lv) || (v == lv && gi > li);
            if (valid && (v < bv || (v == bv && gi < bi))){ bv = v; bi = gi; }
        }
        sv[tid] = bv; si[tid] = bi;
        __syncthreads();
        for (int st = 128; st > 0; st >>= 1){
            if (tid < st){
                float ov = sv[tid+st]; int oi = si[tid+st];
                if (ov < sv[tid] || (ov == sv[tid] && oi < si[tid])){ sv[tid]=ov; si[tid]=oi; }
            }
            __syncthreads();
        }
        if (tid == 0){ g_idx[b*TOPK_+r] = si[0]; last_v = sv[0]; last_i = si[0]; }
        __syncthreads();
    }
}

__global__ __launch_bounds__(64)
void gather_kv_kernel(const float* __restrict__ rdata,
                      const float* __restrict__ gc, const float* __restrict__ bc,
                      const float* __restrict__ wk, const float* __restrict__ wv){
    int rid = blockIdx.x, tid = threadIdx.x;
    long row = g_idx[rid];
    const float* r = rdata + row*DD;
    __shared__ float c_sh[DD];
    __shared__ float r1[64], r2[64];
    float vals[5]; float s = 0.f, sq = 0.f;
    #pragma unroll
    for (int e = 0; e < 5; e++){
        int j = tid + 64*e;
        float v = (j < DD) ? r[j] : 0.f;
        vals[e] = v; s += v; sq += v*v;
    }
    r1[tid] = s; r2[tid] = sq;
    __syncthreads();
    for (int st = 32; st > 0; st >>= 1){
        if (tid < st){ r1[tid] += r1[tid+st]; r2[tid] += r2[tid+st]; }
        __syncthreads();
    }
    float mean = r1[0]*(1.f/266.f);
    float rstd = rsqrtf(r2[0]*(1.f/266.f) - mean*mean + EPS_);
    #pragma unroll
    for (int e = 0; e < 5; e++){
        int j = tid + 64*e;
        if (j < DD) c_sh[j] = (vals[e]-mean)*rstd*gc[j] + bc[j];
    }
    __syncthreads();
    float ka = 0.f;
    #pragma unroll 4
    for (int j = 0; j < 256; j++) ka = fmaf(c_sh[j], wk[j*64+tid], ka);
    float va = 0.f;
    #pragma unroll
    for (int j = 0; j < 10; j++) va = fmaf(c_sh[256+j], wv[j*64+tid], va);
    g_k[(long)rid*64 + tid] = ka;
    g_v[(long)rid*64 + tid] = va;
}

// attention: grid (32 x 4), 64 threads, 1 token/thread
__global__ __launch_bounds__(64)
void attn_kernel(){
    int b = blockIdx.x, qq = blockIdx.y;
    int tid = threadIdx.x;
    __shared__ float k_sh[TOPK_*64];
    __shared__ float v_sh[TOPK_*64];
    for (int idx = tid; idx < TOPK_*64; idx += 64){
        k_sh[idx] = g_k[(long)b*TOPK_*64 + idx];
        v_sh[idx] = g_v[(long)b*TOPK_*64 + idx];
    }
    __syncthreads();
    int n = qq*64 + tid;
    const float4* qr = (const float4*)(g_q + ((long)b*HWP + n)*64);
    float4 q4[16];
    #pragma unroll
    for (int i = 0; i < 16; i++) q4[i] = qr[i];
    float sim[32]; float mx = -INFINITY;
    #pragma unroll
    for (int j = 0; j < 32; j++){
        const float4* k4 = (const float4*)&k_sh[j*64];
        float a = 0.f;
        #pragma unroll
        for (int i = 0; i < 16; i++){
            float4 kv = k4[i];
            a += q4[i].x*kv.x + q4[i].y*kv.y + q4[i].z*kv.z + q4[i].w*kv.w;
        }
        a *= 0.125f;
        sim[j] = a; mx = fmaxf(mx, a);
    }
    float den = 0.f;
    #pragma unroll
    for (int j = 0; j < 32; j++){ sim[j] = expf(sim[j]-mx); den += sim[j]; }
    float inv = 1.f/den;
    float o[64];
    #pragma unroll
    for (int i = 0; i < 64; i++) o[i] = 0.f;
    #pragma unroll
    for (int j = 0; j < 32; j++){
        float a = sim[j]*inv;
        #pragma unroll
        for (int i = 0; i < 64; i++) o[i] = fmaf(a, v_sh[j*64+i], o[i]);
    }
    float4* orow = (float4*)(g_o + ((long)b*HWP + n)*64);
    #pragma unroll
    for (int i = 0; i < 16; i++)
        orow[i] = make_float4(o[4*i], o[4*i+1], o[4*i+2], o[4*i+3]);
}

// ============ wo-proj (tf32 mma) + residual + LN_ff, 32 rows/block ============
__global__ __launch_bounds__(256)
void woln_mma(const float* __restrict__ wo, const float* __restrict__ bo,
              const float* __restrict__ gf, const float* __restrict__ bf){
    extern __shared__ float smw[];
    float* os = smw;              // [k=64][m=33]
    float* ts = smw + 64*33;      // [32][257]
    __shared__ float gb[512];
    int tid = threadIdx.x, lane = tid&31, wid = tid>>5;
    int gid = lane>>2, tig = lane&3;
    int r0 = blockIdx.x*32;
    gb[tid] = gf[tid]; gb[256+tid] = bf[tid];
    for (int idx = tid; idx < 2048; idx += 256){
        int m = idx >> 6, d = idx & 63;
        os[d*33 + m] = to_tf32(g_o[(long)(r0+m)*64 + d]);
    }
    __syncthreads();
    int warp_m = wid & 1, warp_n = wid >> 1;
    int m0 = warp_m*16, n0w = warp_n*64;
    float acc[8][4];
    #pragma unroll
    for (int j = 0; j < 8; j++)
      #pragma unroll
      for (int i = 0; i < 4; i++) acc[j][i] = 0.f;
    for (int ks = 0; ks < 8; ks++){
        int k0 = ks*8;
        uint32_t a[4];
        a[0] = __float_as_uint(os[(k0+tig)*33 + m0+gid]);
        a[1] = __float_as_uint(os[(k0+tig)*33 + m0+gid+8]);
        a[2] = __float_as_uint(os[(k0+tig+4)*33 + m0+gid]);
        a[3] = __float_as_uint(os[(k0+tig+4)*33 + m0+gid+8]);
        #pragma unroll
        for (int jn = 0; jn < 8; jn++){
            int col = n0w + jn*8 + gid;
            uint32_t b0 = __float_as_uint(to_tf32(wo[(k0+tig)*256 + col]));
            uint32_t b1 = __float_as_uint(to_tf32(wo[(k0+tig+4)*256 + col]));
            mma8(acc[jn], a, b0, b1);
        }
    }
    #pragma unroll
    for (int jn = 0; jn < 8; jn++){
        int c = n0w + jn*8 + tig*2;
        float bc0 = bo[c], bc1 = bo[c+1];
        #pragma unroll
        for (int half = 0; half < 2; half++){
            int r = m0 + gid + half*8;
            float2 res = *(const float2*)(g_t + (long)(r0+r)*256 + c);
            float v0 = acc[jn][half*2+0] + bc0 + res.x;
            float v1 = acc[jn][half*2+1] + bc1 + res.y;
            *(float2*)(g_t + (long)(r0+r)*256 + c) = make_float2(v0, v1);
            ts[r*257 + c] = v0;
            ts[r*257 + c + 1] = v1;
        }
    }
    __syncthreads();
    int l = lane;
    for (int rr = 0; rr < 4; rr++){
        int r = wid*4 + rr;
        float s = 0.f, sq = 0.f;
        float vv[8];
        #pragma unroll
        for (int e = 0; e < 8; e++){ float v = ts[r*257 + l+32*e]; vv[e]=v; s += v; sq += v*v; }
        s = wsum(s); sq = wsum(sq);
        float mean = s*(1.f/256.f);
        float rstd = rsqrtf(sq*(1.f/256.f) - mean*mean + EPS_);
        #pragma unroll
        for (int e = 0; e < 8; e++){
            int j = l+32*e;
            g_lnf[(long)(r0+r)*256 + j] = (vv[e]-mean)*rstd*gb[j] + gb[256+j];
        }
    }
}

// FFN GEMM1
__global__ __launch_bounds__(256)
void ffn1_mma(const float* __restrict__ w1, const float* __restrict__ b1){
    __shared__ float As2[2][16][73];
    __shared__ float Bs[2][16][136];
    int tid = threadIdx.x, lane = tid&31, wid = tid>>5;
    int gid = lane>>2, tig = lane&3;
    int warp_m = wid&3, warp_n = wid>>2;
    int r0 = blockIdx.y*64, cn0 = blockIdx.x*64;

    float acc[8][4];
    #pragma unroll
    for (int j = 0; j < 8; j++)
      #pragma unroll
      for (int i = 0; i < 4; i++) acc[j][i] = 0.f;

    int am = tid>>2, akq = tid&3;
    auto stage = [&](int kc){
        int bf = kc&1, k0 = kc*16;
        float4 av = *(const float4*)(g_lnf + (long)(r0+am)*256 + k0 + akq*4);
        As2[bf][akq*4+0][am] = to_tf32(av.x);
        As2[bf][akq*4+1][am] = to_tf32(av.y);
        As2[bf][akq*4+2][am] = to_tf32(av.z);
        As2[bf][akq*4+3][am] = to_tf32(av.w);
        #pragma unroll
        for (int rep = 0; rep < 8; rep++){
            int linear = rep*256 + tid;
            int kr = linear>>7, c = linear&127;
            int src = (c < 64) ? (cn0 + c) : (256 + cn0 + c - 64);
            Bs[bf][kr][c] = to_tf32(w1[(long)(k0+kr)*512 + src]);
        }
    };
    stage(0);
    __syncthreads();
    int m0 = warp_m*16;
    for (int kc = 0; kc < 16; kc++){
        if (kc < 15) stage(kc+1);
        int bf = kc&1;
        #pragma unroll
        for (int ks = 0; ks < 2; ks++){
            uint32_t a[4];
            a[0] = __float_as_uint(As2[bf][ks*8+tig][m0+gid]);
            a[1] = __float_as_uint(As2[bf][ks*8+tig][m0+gid+8]);
            a[2] = __float_as_uint(As2[bf][ks*8+tig+4][m0+gid]);
            a[3] = __float_as_uint(As2[bf][ks*8+tig+4][m0+gid+8]);
            #pragma unroll
            for (int jn = 0; jn < 8; jn++){
                int col = (jn < 4) ? (warp_n*32 + jn*8 + gid)
                                   : (64 + warp_n*32 + (jn-4)*8 + gid);
                uint32_t b0 = __float_as_uint(Bs[bf][ks*8+tig][col]);
                uint32_t b1v = __float_as_uint(Bs[bf][ks*8+tig+4][col]);
                mma8(acc[jn], a, b0, b1v);
            }
        }
        __syncthreads();
    }
    #pragma unroll
    for (int jn = 0; jn < 4; jn++){
        int c = cn0 + warp_n*32 + jn*8 + tig*2;
        float ba0 = b1[c], ba1 = b1[c+1];
        float bg0 = b1[256+c], bg1 = b1[256+c+1];
        #pragma unroll
        for (int half = 0; half < 2; half++){
            int r = r0 + warp_m*16 + gid + half*8;
            float ha0 = acc[jn][half*2+0] + ba0;
            float ha1 = acc[jn][half*2+1] + ba1;
            float hg0 = acc[jn+4][half*2+0] + bg0;
            float hg1 = acc[jn+4][half*2+1] + bg1;
            *(float2*)(g_out1 + (long)r*256 + c) =
                make_float2(ha0*gelu_exact(hg0), ha1*gelu_exact(hg1));
        }
    }
}

// FFN GEMM2
__global__ __launch_bounds__(256)
void ffn2_mma(const float* __restrict__ w2, const float* __restrict__ b2,
              float* __restrict__ out){
    __shared__ float As2[2][16][73];
    __shared__ float Bs[2][16][72];
    int tid = threadIdx.x, lane = tid&31, wid = tid>>5;
    int gid = lane>>2, tig = lane&3;
    int warp_m = wid&3, warp_n = wid>>2;
    int r0 = blockIdx.y*64, cn0 = blockIdx.x*64;

    float acc[4][4];
    #pragma unroll
    for (int j = 0; j < 4; j++)
      #pragma unroll
      for (int i = 0; i < 4; i++) acc[j][i] = 0.f;

    int am = tid>>2, akq = tid&3;
    auto stage = [&](int kc){
        int bf = kc&1, k0 = kc*16;
        float4 av = *(const float4*)(g_out1 + (long)(r0+am)*256 + k0 + akq*4);
        As2[bf][akq*4+0][am] = to_tf32(av.x);
        As2[bf][akq*4+1][am] = to_tf32(av.y);
        As2[bf][akq*4+2][am] = to_tf32(av.z);
        As2[bf][akq*4+3][am] = to_tf32(av.w);
        #pragma unroll
        for (int rep = 0; rep < 4; rep++){
            int linear = rep*256 + tid;
            int kr = linear>>6, c = linear&63;
            Bs[bf][kr][c] = to_tf32(w2[(long)(k0+kr)*256 + cn0 + c]);
        }
    };
    stage(0);
    __syncthreads();
    int m0 = warp_m*16;
    for (int kc = 0; kc < 16; kc++){
        if (kc < 15) stage(kc+1);
        int bf = kc&1;
        #pragma unroll
        for (int ks = 0; ks < 2; ks++){
            uint32_t a[4];
            a[0] = __float_as_uint(As2[bf][ks*8+tig][m0+gid]);
            a[1] = __float_as_uint(As2[bf][ks*8+tig][m0+gid+8]);
            a[2] = __float_as_uint(As2[bf][ks*8+tig+4][m0+gid]);
            a[3] = __float_as_uint(As2[bf][ks*8+tig+4][m0+gid+8]);
            #pragma unroll
            for (int jn = 0; jn < 4; jn++){
                int col = warp_n*32 + jn*8 + gid;
                uint32_t b0 = __float_as_uint(Bs[bf][ks*8+tig][col]);
                uint32_t b1v = __float_as_uint(Bs[bf][ks*8+tig+4][col]);
                mma8(acc[jn], a, b0, b1v);
            }
        }
        __syncthreads();
    }
    #pragma unroll
    for (int jn = 0; jn < 4; jn++){
        int c = cn0 + warp_n*32 + jn*8 + tig*2;
        float bc0 = b2[c], bc1 = b2[c+1];
        #pragma unroll
        for (int half = 0; half < 2; half++){
            int r = r0 + warp_m*16 + gid + half*8;
            float2 res = *(const float2*)(g_t + (long)r*256 + c);
            float v0 = acc[jn][half*2+0] + bc0 + res.x;
            float v1 = acc[jn][half*2+1] + bc1 + res.y;
            int b = r >> 8, p = r & 255;
            out[((long)b*256 + c)*256 + p]   = v0;
            out[((long)b*256 + c+1)*256 + p] = v1;
        }
    }
}

extern "C" void kernel_launch(void* const* d_in, const int* in_sizes, int n_in,
                              void* d_out, int out_size) {
    const float* x       = (const float*)d_in[0];
    const float* conv1_w = (const float*)d_in[1];
    const float* conv2_w = (const float*)d_in[2];
    const float* bn1_g   = (const float*)d_in[3];
    const float* bn1_b   = (const float*)d_in[4];
    const float* bn2_g   = (const float*)d_in[5];
    const float* bn2_b   = (const float*)d_in[6];
    const float* rdata   = (const float*)d_in[7];
    const float* ln_attn_g = (const float*)d_in[8];
    const float* ln_attn_b = (const float*)d_in[9];
    const float* ln_ctx_g  = (const float*)d_in[10];
    const float* ln_ctx_b  = (const float*)d_in[11];
    const float* wq  = (const float*)d_in[12];
    const float* wk  = (const float*)d_in[13];
    const float* wv  = (const float*)d_in[14];
    const float* wqe = (const float*)d_in[15];
    const float* wo  = (const float*)d_in[16];
    const float* bo  = (const float*)d_in[17];
    const float* ln_ff_g = (const float*)d_in[18];
    const float* ln_ff_b = (const float*)d_in[19];
    const float* w1  = (const float*)d_in[20];
    const float* b1  = (const float*)d_in[21];
    const float* w2  = (const float*)d_in[22];
    const float* b2  = (const float*)d_in[23];
    float* out = (float*)d_out;

    const int conv_smem  = (2*AS_BUF + 2*XS_BUF) * 4;   // 99328 B
    const int score_smem = (8448 + 32 + 32*33) * 4;     // 38144 B
    const int lnq_smem   = 256*33*4;
    const int woln_smem  = (64*33 + 32*257)*4;
    cudaFuncSetAttribute(conv_mma_kernel<1>, cudaFuncAttributeMaxDynamicSharedMemorySize, conv_smem);
    cudaFuncSetAttribute(conv_mma_kernel<2>, cudaFuncAttributeMaxDynamicSharedMemorySize, conv_smem);
    cudaFuncSetAttribute(score_mma_kernel, cudaFuncAttributeMaxDynamicSharedMemorySize, score_smem);
    cudaFuncSetAttribute(lnq_mma, cudaFuncAttributeMaxDynamicSharedMemorySize, lnq_smem);
    cudaFuncSetAttribute(woln_mma, cudaFuncAttributeMaxDynamicSharedMemorySize, woln_smem);

    wtrans2_kernel<<<512, 256>>>(conv1_w, conv2_w);
    conv_mma_kernel<1><<<128, 512, conv_smem>>>(x, bn1_g, bn1_b);
    conv_mma_kernel<2><<<128, 512, conv_smem>>>(x, bn2_g, bn2_b);
    lnq_mma<<<288, 256, lnq_smem>>>(ln_attn_g, ln_attn_b, wq, wqe);
    score_mma_kernel<<<3125, 256, score_smem>>>(rdata, ln_ctx_g, ln_ctx_b);
    scan_kernel<<<32, 256>>>();
    compact_kernel<<<dim3(13,32), 1024>>>();
    rescore_refine<<<32, 256>>>(rdata, ln_ctx_g, ln_ctx_b);
    gather_kv_kernel<<<1024, 64>>>(rdata, ln_ctx_g, ln_ctx_b, wk, wv);
    attn_kernel<<<dim3(32,4), 64>>>();
    woln_mma<<<256, 256, woln_smem>>>(wo, bo, ln_ff_g, ln_ff_b);
    ffn1_mma<<<dim3(4,128), 256>>>(w1, b1);
    ffn2_mma<<<dim3(4,128), 256>>>(w2, b2, out);
}